// round 8
// baseline (speedup 1.0000x reference)
#include <cuda_runtime.h>
#include <cuda_fp16.h>
#include <cstdint>

#define BB 64
#define TT 512
#define DD 256
#define UU 512
#define NCTA 128
#define NTH 288           // 8 compute warps + 1 poller warp
#define WROW 520          // weight row stride (floats)

// dynamic smem layout for lstm kernel
#define H_BYTES  (64 * 2048)                     // h staging [64][512] f32, swizzled
#define W_OFF    H_BYTES                         // 131072
#define W_BYTES  (3 * 4 * WROW * 4)              // 24960
#define R_OFF    (W_OFF + W_BYTES)               // 156032
#define R_BYTES  (256 * 20 * 4)                  // 20480
#define FLAG_OFF (R_OFF + R_BYTES)               // 176512
#define SM_TOTAL (FLAG_OFF + 16)                 // 176528

// Scratch (static device arrays; no cudaMalloc anywhere).
__device__ float  g_xp[3][TT][BB][UU];     // input projections [g][t][b][u]
__device__ __half g_hbuf[2][BB * UU];      // ping-pong hidden state (fp16!)
__device__ unsigned g_count;               // grid barrier counter

// ---- packed f32x2 helpers (full-rate fp32 on sm_103a) ----
__device__ __forceinline__ void fma2(unsigned long long &d, unsigned long long a,
                                     unsigned long long b) {
    asm("fma.rn.f32x2 %0, %1, %2, %0;" : "+l"(d) : "l"(a), "l"(b));
}
__device__ __forceinline__ float2 upk(unsigned long long v) {
    float2 r;
    asm("mov.b64 {%0, %1}, %2;" : "=f"(r.x), "=f"(r.y) : "l"(v));
    return r;
}

__device__ __forceinline__ float fsig(float x) {
    return __fdividef(1.0f, 1.0f + __expf(-x));
}
__device__ __forceinline__ float ftanh(float x) {
    float e = __expf(-2.0f * fabsf(x));
    float r = __fdividef(1.0f - e, 1.0f + e);
    return copysignf(r, x);
}

// ============================================================================
// Phase 1: xp[g][t][b][u] = x[b,t,:] @ w_xg[:,u] + b_g[u]   (unchanged)
// ============================================================================
__global__ void __launch_bounds__(256, 2) proj_kernel(
    const float* __restrict__ x,
    const float* __restrict__ wxi, const float* __restrict__ wxf,
    const float* __restrict__ wxc,
    const float* __restrict__ bi, const float* __restrict__ bf,
    const float* __restrict__ bc) {
    __shared__ __align__(16) float xs[64][33];
    __shared__ __align__(16) float ws[3][32][64];

    const int tid = threadIdx.x;
    const int t = blockIdx.y;
    const int ub = blockIdx.x * 64;

    if (blockIdx.x == 0 && blockIdx.y == 0 && tid == 0) g_count = 0u;

    const int ug = tid & 15;
    const int bg = tid >> 4;
    const int ul = ug << 2;
    const int b0 = bg << 2;

    unsigned long long acc[3][4][2];
#pragma unroll
    for (int g = 0; g < 3; ++g)
#pragma unroll
        for (int i = 0; i < 4; ++i) { acc[g][i][0] = 0ull; acc[g][i][1] = 0ull; }

    for (int k0 = 0; k0 < DD; k0 += 32) {
#pragma unroll
        for (int i = 0; i < 8; ++i) {
            int idx = tid + i * 256;
            int bb = idx >> 5, kk = idx & 31;
            xs[bb][kk] = x[(bb * TT + t) * DD + k0 + kk];
        }
#pragma unroll
        for (int i = 0; i < 24; ++i) {
            int idx = tid + i * 256;
            int g = idx >> 11, r = idx & 2047, kk = r >> 6, uu = r & 63;
            const float* w = (g == 0) ? wxi : ((g == 1) ? wxf : wxc);
            ws[g][kk][uu] = w[(k0 + kk) * UU + ub + uu];
        }
        __syncthreads();
#pragma unroll
        for (int kk = 0; kk < 32; ++kk) {
            unsigned long long xb[4];
#pragma unroll
            for (int i = 0; i < 4; ++i) {
                unsigned xv = __float_as_uint(xs[b0 + i][kk]);
                asm("mov.b64 %0, {%1, %1};" : "=l"(xb[i]) : "r"(xv));
            }
#pragma unroll
            for (int g = 0; g < 3; ++g) {
                const ulonglong2 wv = *(const ulonglong2*)&ws[g][kk][ul];
#pragma unroll
                for (int i = 0; i < 4; ++i) {
                    fma2(acc[g][i][0], xb[i], wv.x);
                    fma2(acc[g][i][1], xb[i], wv.y);
                }
            }
        }
        __syncthreads();
    }

    const float* biases[3] = {bi, bf, bc};
#pragma unroll
    for (int g = 0; g < 3; ++g) {
        float2 bv0 = *(const float2*)&biases[g][ub + ul];
        float2 bv1 = *(const float2*)&biases[g][ub + ul + 2];
#pragma unroll
        for (int i = 0; i < 4; ++i) {
            float2 r0 = upk(acc[g][i][0]);
            float2 r1 = upk(acc[g][i][1]);
            r0.x += bv0.x; r0.y += bv0.y;
            r1.x += bv1.x; r1.y += bv1.y;
            float* dst = &g_xp[g][t][b0 + i][ub + ul];
            *(float2*)dst = r0;
            *(float2*)(dst + 2) = r1;
        }
    }
}

// ============================================================================
// Init: h0 -> g_hbuf[1] (fp16)
// ============================================================================
__global__ void init_kernel(const float* __restrict__ h0) {
    int i = blockIdx.x * blockDim.x + threadIdx.x;
    if (i < BB * UU) g_hbuf[1][i] = __float2half_rn(h0[i]);
}

// ============================================================================
// Phase 2: persistent recurrent kernel. 128 CTAs x 288 threads.
// Warps 0..7 compute; warp 8 = dedicated grid-barrier poller.
// Thread (ks=tid>>6 in 0..3, bg=(tid>>2)&15, c=tid&3): rows bg*4..+3,
// k in [ks*128, ks*128+128). Warp (half=w&1, ks) self-stages its own region
// (rows [half*32,+32) x 128 k): fp16 LDG.cg -> cvt -> swizzled fp32 STS,
// then __syncwarp only -- no CTA sync before compute.
// h smem: row r at r*2048; fp32 16B-slot s at s ^ ((r>>2)&7) -> 1-phase LDS.
// Sync per step: one __syncthreads; gates -> membar.cta + bar.arrive(1,288);
// poller: bar.sync(1,288) -> red.add.release.gpu -> poll -> smem flag release.
// ============================================================================
__global__ void __launch_bounds__(NTH, 1) lstm_kernel(
    const float* __restrict__ whi, const float* __restrict__ whf,
    const float* __restrict__ whc, const float* __restrict__ c0,
    float* __restrict__ out) {
    extern __shared__ __align__(16) char sm[];
    float* smW = (float*)(sm + W_OFF);
    float* smR = (float*)(sm + R_OFF);

    const int tid = threadIdx.x;
    const int w = tid >> 5, lane = tid & 31;
    const int u0 = blockIdx.x * 4;
    // compute roles (tid < 256)
    const int c  = tid & 3;
    const int bg = (tid >> 2) & 15;
    const int ks = (tid >> 6) & 3;
    const int key = bg & 7;                  // swizzle key for this thread's rows
    // staging roles (warp-local)
    const int half = w & 1;
    const int fs = lane & 15;                // 16B fp16-chunk within k-region
    const int ro = lane >> 4;                // row parity
    // gate roles
    const int b2 = (tid < 256) ? (tid >> 2) : 0;
    const int c2 = tid & 3;
    const int u = u0 + c2;

    {
        const float* wsrc[3] = {whi, whf, whc};
        for (int i = tid; i < 3 * 4 * UU; i += NTH) {
            int cc = i & 3, k = (i >> 2) & 511, g = i >> 11;
            smW[(g * 4 + cc) * WROW + k] = wsrc[g][k * UU + u0 + cc];
        }
    }
    float cst = (tid < 256) ? c0[b2 * UU + u] : 0.0f;

    const uint32_t smbase = (uint32_t)__cvta_generic_to_shared(sm);
    const uint32_t flagaddr = smbase + FLAG_OFF;
    if (tid == 0) *(unsigned*)(sm + FLAG_OFF) = 0u;

    const float* wp0 = smW + (0 * 4 + c) * WROW + ks * 128;
    const float* wp1 = smW + (1 * 4 + c) * WROW + ks * 128;
    const float* wp2 = smW + (2 * 4 + c) * WROW + ks * 128;
    const char* hrow = sm + (bg * 4) * 2048;                  // rows bg*4..+3
    float* redw = smR + (bg * 16 + c) * 20 + (ks ^ (bg & 3)); // + i*80 + g*4
    const float* redr = smR + tid * 20;

    const size_t gstride = (size_t)TT * BB * UU;
    const float* xpi = &g_xp[0][0][0][0] + 0 * gstride + (size_t)b2 * UU + u;
    const float* xpf = &g_xp[0][0][0][0] + 1 * gstride + (size_t)b2 * UU + u;
    const float* xpc = &g_xp[0][0][0][0] + 2 * gstride + (size_t)b2 * UU + u;
    float* orow = out + (size_t)b2 * TT * UU + u;

    __syncthreads();

    for (int t = 0; t < TT; ++t) {
        if (tid < 256) {
            // prefetch xp(t) before the flag wait (independent of recurrence)
            float pi = __ldcg(xpi + (size_t)t * (BB * UU));
            float pf = __ldcg(xpf + (size_t)t * (BB * UU));
            float pc = __ldcg(xpc + (size_t)t * (BB * UU));

            if (t > 0) {
                unsigned v;
                do {
                    asm volatile("ld.acquire.cta.shared.u32 %0, [%1];"
                                 : "=r"(v) : "r"(flagaddr) : "memory");
                } while (v < (unsigned)t);
            }

            // stage THIS warp's h region: fp16 -> fp32, swizzled smem
            const __half* hsrc = &g_hbuf[(t + 1) & 1][0];
#pragma unroll
            for (int j = 0; j < 16; ++j) {
                int r = half * 32 + j * 2 + ro;
                float4 raw = __ldcg(
                    (const float4*)(hsrc + (r << 9) + ks * 128 + fs * 8));
                float2 f0 = __half22float2(*(__half2*)&raw.x);
                float2 f1 = __half22float2(*(__half2*)&raw.y);
                float2 f2 = __half22float2(*(__half2*)&raw.z);
                float2 f3 = __half22float2(*(__half2*)&raw.w);
                int rk = (r >> 2) & 7;
                int S = ks * 32 + fs * 2;
                *(float4*)(sm + r * 2048 + ((S ^ rk) << 4)) =
                    make_float4(f0.x, f0.y, f1.x, f1.y);
                *(float4*)(sm + r * 2048 + (((S + 1) ^ rk) << 4)) =
                    make_float4(f2.x, f2.y, f3.x, f3.y);
            }
            __syncwarp();

            unsigned long long acc[4][3];
#pragma unroll
            for (int i = 0; i < 4; ++i)
#pragma unroll
                for (int g = 0; g < 3; ++g) acc[i][g] = 0ull;

#pragma unroll 8
            for (int k4 = 0; k4 < 32; ++k4) {
                const ulonglong2 v0 = *(const ulonglong2*)(wp0 + k4 * 4);
                const ulonglong2 v1 = *(const ulonglong2*)(wp1 + k4 * 4);
                const ulonglong2 v2 = *(const ulonglong2*)(wp2 + k4 * 4);
                const uint32_t koff = (uint32_t)((ks * 32 + (k4 ^ key)) << 4);
#pragma unroll
                for (int i = 0; i < 4; ++i) {
                    const ulonglong2 hv =
                        *(const ulonglong2*)(hrow + i * 2048 + koff);
                    fma2(acc[i][0], hv.x, v0.x);
                    fma2(acc[i][1], hv.x, v1.x);
                    fma2(acc[i][2], hv.x, v2.x);
                    fma2(acc[i][0], hv.y, v0.y);
                    fma2(acc[i][1], hv.y, v1.y);
                    fma2(acc[i][2], hv.y, v2.y);
                }
            }

#pragma unroll
            for (int i = 0; i < 4; ++i)
#pragma unroll
                for (int g = 0; g < 3; ++g) {
                    float2 v = upk(acc[i][g]);
                    redw[i * 80 + g * 4] = v.x + v.y;
                }
            __syncthreads();

            // reduce + gates
            float s[3];
#pragma unroll
            for (int g = 0; g < 3; ++g) {
                float4 a = *(const float4*)(redr + g * 4);
                s[g] = (a.x + a.y) + (a.z + a.w);
            }
            float ig = fsig(pi + s[0]);
            float fg = fsig(pf + s[1]);
            float cin = ftanh(pc + s[2]);
            cst = fg * cst + ig * cin;
            float hn = ftanh(cst);
            unsigned short hb =
                __half_as_ushort(__float2half_rn(hn));
            asm volatile("st.global.cg.u16 [%0], %1;"
                         :: "l"(&g_hbuf[t & 1][b2 * UU + u]), "h"(hb)
                         : "memory");
            orow[(size_t)t * UU] = hn;

            if (t < TT - 1) {
                asm volatile("membar.cta;" ::: "memory");
                asm volatile("bar.arrive 1, %0;" :: "n"(NTH) : "memory");
            }
        } else {
            __syncthreads();
            if (t < TT - 1) {
                asm volatile("bar.sync 1, %0;" :: "n"(NTH) : "memory");
                if (lane == 0) {
                    asm volatile("red.release.gpu.global.add.u32 [%0], 1;"
                                 :: "l"(&g_count) : "memory");
                    unsigned target = (unsigned)(t + 1) * NCTA;
                    unsigned v;
                    do {
                        asm volatile("ld.acquire.gpu.u32 %0, [%1];"
                                     : "=r"(v) : "l"(&g_count) : "memory");
                    } while (v < target);
                    asm volatile("st.release.cta.shared.u32 [%0], %1;"
                                 :: "r"(flagaddr), "r"((unsigned)(t + 1))
                                 : "memory");
                }
                __syncwarp();
            }
        }
    }
}

extern "C" void kernel_launch(void* const* d_in, const int* in_sizes, int n_in,
                              void* d_out, int out_size) {
    const float* x   = (const float*)d_in[0];
    const float* wxi = (const float*)d_in[1];
    const float* wxf = (const float*)d_in[2];
    const float* wxc = (const float*)d_in[3];
    const float* whi = (const float*)d_in[4];
    const float* whf = (const float*)d_in[5];
    const float* whc = (const float*)d_in[6];
    const float* bi  = (const float*)d_in[7];
    const float* bf  = (const float*)d_in[8];
    const float* bc  = (const float*)d_in[9];
    const float* h0  = (const float*)d_in[10];
    const float* c0  = (const float*)d_in[11];
    float* out = (float*)d_out;

    cudaFuncSetAttribute(lstm_kernel, cudaFuncAttributeMaxDynamicSharedMemorySize,
                         SM_TOTAL);

    proj_kernel<<<dim3(8, TT), 256>>>(x, wxi, wxf, wxc, bi, bf, bc);
    init_kernel<<<(BB * UU + 255) / 256, 256>>>(h0);
    lstm_kernel<<<NCTA, NTH, SM_TOTAL>>>(whi, whf, whc, c0, out);
}

// round 9
// speedup vs baseline: 1.1711x; 1.1711x over previous
#include <cuda_runtime.h>
#include <cstdint>

#define BB 64
#define TT 512
#define DD 256
#define UU 512
#define NCTA 128
#define NTH 288           // 8 compute warps + 1 poller warp
#define WROW 520          // weight row stride (floats): col rows 8 banks apart
#define REDO 52           // reduction out-stride (floats), 16B-aligned, padded

// dynamic smem layout for lstm kernel
#define H_BYTES  (64 * 2048)                     // h staging [64][512] f32, swizzled
#define W_OFF    H_BYTES                         // 131072
#define W_BYTES  (3 * 4 * WROW * 4)              // 24960
#define R_OFF    (W_OFF + W_BYTES)               // 156032
#define R_BYTES  (256 * REDO * 4)                // 53248
#define FLAG_OFF (R_OFF + R_BYTES)               // 209280
#define SM_TOTAL (FLAG_OFF + 16)                 // 209296

// Scratch (static device arrays; no cudaMalloc anywhere).
__device__ float g_xp[3][TT][BB][UU];      // input projections [g][t][b][u]
__device__ float g_hbuf[2][BB * UU];       // ping-pong hidden state (fp32)
__device__ unsigned g_count;               // grid barrier counter

// ---- packed f32x2 helpers (full-rate fp32 on sm_103a) ----
__device__ __forceinline__ void fma2(unsigned long long &d, unsigned long long a,
                                     unsigned long long b) {
    asm("fma.rn.f32x2 %0, %1, %2, %0;" : "+l"(d) : "l"(a), "l"(b));
}
__device__ __forceinline__ float2 upk(unsigned long long v) {
    float2 r;
    asm("mov.b64 {%0, %1}, %2;" : "=f"(r.x), "=f"(r.y) : "l"(v));
    return r;
}
__device__ __forceinline__ void cp16(uint32_t dst, const float* src) {
    asm volatile("cp.async.cg.shared.global [%0], [%1], 16;" :: "r"(dst), "l"(src));
}

__device__ __forceinline__ float fsig(float x) {
    return __fdividef(1.0f, 1.0f + __expf(-x));
}
__device__ __forceinline__ float ftanh(float x) {
    float e = __expf(-2.0f * fabsf(x));
    float r = __fdividef(1.0f - e, 1.0f + e);
    return copysignf(r, x);
}

// ============================================================================
// Phase 1: xp[g][t][b][u] = x[b,t,:] @ w_xg[:,u] + b_g[u]   (unchanged)
// ============================================================================
__global__ void __launch_bounds__(256, 2) proj_kernel(
    const float* __restrict__ x,
    const float* __restrict__ wxi, const float* __restrict__ wxf,
    const float* __restrict__ wxc,
    const float* __restrict__ bi, const float* __restrict__ bf,
    const float* __restrict__ bc) {
    __shared__ __align__(16) float xs[64][33];
    __shared__ __align__(16) float ws[3][32][64];

    const int tid = threadIdx.x;
    const int t = blockIdx.y;
    const int ub = blockIdx.x * 64;

    if (blockIdx.x == 0 && blockIdx.y == 0 && tid == 0) g_count = 0u;

    const int ug = tid & 15;
    const int bg = tid >> 4;
    const int ul = ug << 2;
    const int b0 = bg << 2;

    unsigned long long acc[3][4][2];
#pragma unroll
    for (int g = 0; g < 3; ++g)
#pragma unroll
        for (int i = 0; i < 4; ++i) { acc[g][i][0] = 0ull; acc[g][i][1] = 0ull; }

    for (int k0 = 0; k0 < DD; k0 += 32) {
#pragma unroll
        for (int i = 0; i < 8; ++i) {
            int idx = tid + i * 256;
            int bb = idx >> 5, kk = idx & 31;
            xs[bb][kk] = x[(bb * TT + t) * DD + k0 + kk];
        }
#pragma unroll
        for (int i = 0; i < 24; ++i) {
            int idx = tid + i * 256;
            int g = idx >> 11, r = idx & 2047, kk = r >> 6, uu = r & 63;
            const float* w = (g == 0) ? wxi : ((g == 1) ? wxf : wxc);
            ws[g][kk][uu] = w[(k0 + kk) * UU + ub + uu];
        }
        __syncthreads();
#pragma unroll
        for (int kk = 0; kk < 32; ++kk) {
            unsigned long long xb[4];
#pragma unroll
            for (int i = 0; i < 4; ++i) {
                unsigned xv = __float_as_uint(xs[b0 + i][kk]);
                asm("mov.b64 %0, {%1, %1};" : "=l"(xb[i]) : "r"(xv));
            }
#pragma unroll
            for (int g = 0; g < 3; ++g) {
                const ulonglong2 wv = *(const ulonglong2*)&ws[g][kk][ul];
#pragma unroll
                for (int i = 0; i < 4; ++i) {
                    fma2(acc[g][i][0], xb[i], wv.x);
                    fma2(acc[g][i][1], xb[i], wv.y);
                }
            }
        }
        __syncthreads();
    }

    const float* biases[3] = {bi, bf, bc};
#pragma unroll
    for (int g = 0; g < 3; ++g) {
        float2 bv0 = *(const float2*)&biases[g][ub + ul];
        float2 bv1 = *(const float2*)&biases[g][ub + ul + 2];
#pragma unroll
        for (int i = 0; i < 4; ++i) {
            float2 r0 = upk(acc[g][i][0]);
            float2 r1 = upk(acc[g][i][1]);
            r0.x += bv0.x; r0.y += bv0.y;
            r1.x += bv1.x; r1.y += bv1.y;
            float* dst = &g_xp[g][t][b0 + i][ub + ul];
            *(float2*)dst = r0;
            *(float2*)(dst + 2) = r1;
        }
    }
}

// ============================================================================
// Init: h0 -> g_hbuf[1]
// ============================================================================
__global__ void init_kernel(const float* __restrict__ h0) {
    int i = blockIdx.x * blockDim.x + threadIdx.x;
    if (i < BB * UU) g_hbuf[1][i] = h0[i];
}

// ============================================================================
// Phase 2: persistent recurrent kernel. 128 CTAs x 288 threads.
// Warps 0..7 compute; warp 8 = grid-barrier poller.
// Thread (ks=tid>>4 in 0..15, bg=(tid>>1)&7, c=tid&1):
//   8 rows bg*8..+7, 6 outputs (3 gates x cols c*2,c*2+1), 32 k = slots ks*8..+7.
//   -> per k4: 8 h-LDS.128 + 6 w-LDS.128 for 96 fma2 (1.17 B/MAC).
// Warp w self-stages h slots [w*16, w*16+16) (k in [w*64,+64)), all 64 rows.
// h smem: row r at r*2048; 16B slot s stored at s ^ ((r>>3)&7); thread's rows
//   share key bg -> per-thread-constant XOR. ks-pair rotation (+2 slots)
//   keeps w and h bank groups disjoint within a warp.
// Partials: red[o*REDO + g*16 + (ks ^ (bg*2+c))], o=row*4+col; gate thread
//   tid(<256, o=tid) reads 16 contiguous floats/gate (XOR perm absorbed by sum).
// Sync per step: one __syncthreads; gates -> membar.cta + bar.arrive(1,288);
// poller: bar.sync(1,288) -> red.add.release.gpu -> poll -> smem flag release.
// ============================================================================
__global__ void __launch_bounds__(NTH, 1) lstm_kernel(
    const float* __restrict__ whi, const float* __restrict__ whf,
    const float* __restrict__ whc, const float* __restrict__ c0,
    float* __restrict__ out) {
    extern __shared__ __align__(16) char sm[];
    float* smW = (float*)(sm + W_OFF);
    float* smR = (float*)(sm + R_OFF);

    const int tid = threadIdx.x;
    const int wid = tid >> 5, lane = tid & 31;
    const int u0 = blockIdx.x * 4;
    // compute roles (tid < 256)
    const int c  = tid & 1;
    const int bg = (tid >> 1) & 7;
    const int ks = tid >> 4;                 // 0..15 (== wid*2 + ((tid>>4)&1))
    const int rot = (ks & 1) * 2;            // slot rotation for ks pairs
    // staging roles (warp-local): lane = (lr=lane>>3 in 0..3, ls=lane&7)
    const int lr = lane >> 3, ls = lane & 7;
    // gate roles (tid < 256): output o = tid = row*4 + col
    const int b2 = tid >> 2, c2 = tid & 3;
    const int u = u0 + c2;

    {
        const float* wsrc[3] = {whi, whf, whc};
        for (int i = tid; i < 3 * 4 * UU; i += NTH) {
            int cc = i & 3, k = (i >> 2) & 511, g = i >> 11;
            smW[(g * 4 + cc) * WROW + k] = wsrc[g][k * UU + u0 + cc];
        }
    }
    float cst = (tid < 256) ? c0[b2 * UU + u] : 0.0f;

    const uint32_t smbase = (uint32_t)__cvta_generic_to_shared(sm);
    const uint32_t flagaddr = smbase + FLAG_OFF;
    if (tid == 0) *(unsigned*)(sm + FLAG_OFF) = 0u;

    const int perm = bg * 2 + c;                       // ks-XOR bijection
    float* redw = smR + (bg * 8) * 4 * REDO + (c * 2) * REDO + (ks ^ perm);
    const float* redr = smR + tid * REDO;              // o = tid, 16B-aligned

    const size_t gstride = (size_t)TT * BB * UU;
    const float* xpi = &g_xp[0][0][0][0] + 0 * gstride + (size_t)b2 * UU + u;
    const float* xpf = &g_xp[0][0][0][0] + 1 * gstride + (size_t)b2 * UU + u;
    const float* xpc = &g_xp[0][0][0][0] + 2 * gstride + (size_t)b2 * UU + u;
    float* orow = out + (size_t)b2 * TT * UU + u;

    __syncthreads();

    for (int t = 0; t < TT; ++t) {
        if (tid < 256) {
            // prefetch xp(t) before the flag wait (independent of recurrence)
            float pi = __ldcg(xpi + (size_t)t * (BB * UU));
            float pf = __ldcg(xpf + (size_t)t * (BB * UU));
            float pc = __ldcg(xpc + (size_t)t * (BB * UU));

            if (t > 0) {
                unsigned v;
                do {
                    asm volatile("ld.acquire.cta.shared.u32 %0, [%1];"
                                 : "=r"(v) : "r"(flagaddr) : "memory");
                } while (v < (unsigned)t);
            }

            // stage THIS warp's h region: all 64 rows x slots [wid*16,+16)
            const float* hsrc = &g_hbuf[(t + 1) & 1][0];
#pragma unroll
            for (int j = 0; j < 32; ++j) {
                int jr = j & 15, js = j >> 4;
                int r = jr * 4 + lr;
                int s = wid * 16 + js * 8 + ls;
                uint32_t dst = smbase + r * 2048 +
                               (uint32_t)((s ^ ((r >> 3) & 7)) << 4);
                cp16(dst, hsrc + r * 512 + s * 4);
            }
            asm volatile("cp.async.commit_group;");
            asm volatile("cp.async.wait_group 0;");
            __syncwarp();

            unsigned long long acc[8][3][2];
#pragma unroll
            for (int i = 0; i < 8; ++i)
#pragma unroll
                for (int g = 0; g < 3; ++g) {
                    acc[i][g][0] = 0ull; acc[i][g][1] = 0ull;
                }

#pragma unroll
            for (int j = 0; j < 8; ++j) {
                const int k4 = ks * 8 + ((j + rot) & 7);
                ulonglong2 wv[3][2];
#pragma unroll
                for (int g = 0; g < 3; ++g)
#pragma unroll
                    for (int q = 0; q < 2; ++q)
                        wv[g][q] = *(const ulonglong2*)(
                            smW + (g * 4 + c * 2 + q) * WROW + k4 * 4);
                const uint32_t koff = (uint32_t)((k4 ^ bg) << 4);
                const char* hb = sm + (bg * 8) * 2048 + koff;
#pragma unroll
                for (int i = 0; i < 8; ++i) {
                    const ulonglong2 hv = *(const ulonglong2*)(hb + i * 2048);
#pragma unroll
                    for (int g = 0; g < 3; ++g) {
#pragma unroll
                        for (int q = 0; q < 2; ++q) {
                            fma2(acc[i][g][q], hv.x, wv[g][q].x);
                            fma2(acc[i][g][q], hv.y, wv[g][q].y);
                        }
                    }
                }
            }

            // partial writes: red[(bg*8+i)*4*REDO + (c*2+q)*REDO + g*16 + ks^perm]
#pragma unroll
            for (int i = 0; i < 8; ++i)
#pragma unroll
                for (int g = 0; g < 3; ++g)
#pragma unroll
                    for (int q = 0; q < 2; ++q) {
                        float2 v = upk(acc[i][g][q]);
                        redw[i * 4 * REDO + q * REDO + g * 16] = v.x + v.y;
                    }
            __syncthreads();

            // reduce + gates: 16 contiguous partials per gate
            float s[3];
#pragma unroll
            for (int g = 0; g < 3; ++g) {
                const float* rb = redr + g * 16;
                float4 a = *(const float4*)(rb + 0);
                float4 b = *(const float4*)(rb + 4);
                float4 d = *(const float4*)(rb + 8);
                float4 e = *(const float4*)(rb + 12);
                s[g] = (((a.x + a.y) + (a.z + a.w)) + ((b.x + b.y) + (b.z + b.w)))
                     + (((d.x + d.y) + (d.z + d.w)) + ((e.x + e.y) + (e.z + e.w)));
            }
            float ig = fsig(pi + s[0]);
            float fg = fsig(pf + s[1]);
            float cin = ftanh(pc + s[2]);
            cst = fg * cst + ig * cin;
            float hn = ftanh(cst);
            __stcg(&g_hbuf[t & 1][b2 * UU + u], hn);
            orow[(size_t)t * UU] = hn;

            if (t < TT - 1) {
                asm volatile("membar.cta;" ::: "memory");
                asm volatile("bar.arrive 1, %0;" :: "n"(NTH) : "memory");
            }
        } else {
            __syncthreads();
            if (t < TT - 1) {
                asm volatile("bar.sync 1, %0;" :: "n"(NTH) : "memory");
                if (lane == 0) {
                    asm volatile("red.release.gpu.global.add.u32 [%0], 1;"
                                 :: "l"(&g_count) : "memory");
                    unsigned target = (unsigned)(t + 1) * NCTA;
                    unsigned v;
                    do {
                        asm volatile("ld.acquire.gpu.u32 %0, [%1];"
                                     : "=r"(v) : "l"(&g_count) : "memory");
                    } while (v < target);
                    asm volatile("st.release.cta.shared.u32 [%0], %1;"
                                 :: "r"(flagaddr), "r"((unsigned)(t + 1))
                                 : "memory");
                }
                __syncwarp();
            }
        }
    }
}

extern "C" void kernel_launch(void* const* d_in, const int* in_sizes, int n_in,
                              void* d_out, int out_size) {
    const float* x   = (const float*)d_in[0];
    const float* wxi = (const float*)d_in[1];
    const float* wxf = (const float*)d_in[2];
    const float* wxc = (const float*)d_in[3];
    const float* whi = (const float*)d_in[4];
    const float* whf = (const float*)d_in[5];
    const float* whc = (const float*)d_in[6];
    const float* bi  = (const float*)d_in[7];
    const float* bf  = (const float*)d_in[8];
    const float* bc  = (const float*)d_in[9];
    const float* h0  = (const float*)d_in[10];
    const float* c0  = (const float*)d_in[11];
    float* out = (float*)d_out;

    cudaFuncSetAttribute(lstm_kernel, cudaFuncAttributeMaxDynamicSharedMemorySize,
                         SM_TOTAL);

    proj_kernel<<<dim3(8, TT), 256>>>(x, wxi, wxf, wxc, bi, bf, bc);
    init_kernel<<<(BB * UU + 255) / 256, 256>>>(h0);
    lstm_kernel<<<NCTA, NTH, SM_TOTAL>>>(whi, whf, whc, c0, out);
}

// round 10
// speedup vs baseline: 1.1735x; 1.0020x over previous
#include <cuda_runtime.h>
#include <cstdint>

#define BB 64
#define TT 512
#define DD 256
#define UU 512
#define NCTA 128
#define NTH 288           // 8 compute warps + 1 poller warp
#define WROW 520          // weight row stride (floats): col rows 8 banks apart
#define REDO 52           // reduction out-stride (floats), 16B-aligned, padded

// dynamic smem layout for lstm kernel
#define H_BYTES  (64 * 2048)                     // h staging [64][512] f32, swizzled
#define W_OFF    H_BYTES                         // 131072
#define W_BYTES  (3 * 4 * WROW * 4)              // 24960
#define R_OFF    (W_OFF + W_BYTES)               // 156032
#define R_BYTES  (256 * REDO * 4)                // 53248
#define FLAG_OFF (R_OFF + R_BYTES)               // 209280
#define SM_TOTAL (FLAG_OFF + 16)                 // 209296

// Scratch (static device arrays; no cudaMalloc anywhere).
__device__ float g_xp[3][TT][BB][UU];      // input projections [g][t][b][u]
__device__ float g_hbuf[2][BB * UU];       // ping-pong hidden state (fp32)
__device__ unsigned g_count;               // grid barrier counter

// ---- packed f32x2 helpers (full-rate fp32 on sm_103a) ----
__device__ __forceinline__ void fma2(unsigned long long &d, unsigned long long a,
                                     unsigned long long b) {
    asm("fma.rn.f32x2 %0, %1, %2, %0;" : "+l"(d) : "l"(a), "l"(b));
}
__device__ __forceinline__ float2 upk(unsigned long long v) {
    float2 r;
    asm("mov.b64 {%0, %1}, %2;" : "=f"(r.x), "=f"(r.y) : "l"(v));
    return r;
}
__device__ __forceinline__ void cp16(uint32_t dst, const float* src) {
    asm volatile("cp.async.cg.shared.global [%0], [%1], 16;" :: "r"(dst), "l"(src));
}

__device__ __forceinline__ float fsig(float x) {
    return __fdividef(1.0f, 1.0f + __expf(-x));
}
__device__ __forceinline__ float ftanh(float x) {
    float e = __expf(-2.0f * fabsf(x));
    float r = __fdividef(1.0f - e, 1.0f + e);
    return copysignf(r, x);
}

// ============================================================================
// Phase 1: xp[g][t][b][u] = x[b,t,:] @ w_xg[:,u] + b_g[u]   (unchanged)
// ============================================================================
__global__ void __launch_bounds__(256, 2) proj_kernel(
    const float* __restrict__ x,
    const float* __restrict__ wxi, const float* __restrict__ wxf,
    const float* __restrict__ wxc,
    const float* __restrict__ bi, const float* __restrict__ bf,
    const float* __restrict__ bc) {
    __shared__ __align__(16) float xs[64][33];
    __shared__ __align__(16) float ws[3][32][64];

    const int tid = threadIdx.x;
    const int t = blockIdx.y;
    const int ub = blockIdx.x * 64;

    if (blockIdx.x == 0 && blockIdx.y == 0 && tid == 0) g_count = 0u;

    const int ug = tid & 15;
    const int bg = tid >> 4;
    const int ul = ug << 2;
    const int b0 = bg << 2;

    unsigned long long acc[3][4][2];
#pragma unroll
    for (int g = 0; g < 3; ++g)
#pragma unroll
        for (int i = 0; i < 4; ++i) { acc[g][i][0] = 0ull; acc[g][i][1] = 0ull; }

    for (int k0 = 0; k0 < DD; k0 += 32) {
#pragma unroll
        for (int i = 0; i < 8; ++i) {
            int idx = tid + i * 256;
            int bb = idx >> 5, kk = idx & 31;
            xs[bb][kk] = x[(bb * TT + t) * DD + k0 + kk];
        }
#pragma unroll
        for (int i = 0; i < 24; ++i) {
            int idx = tid + i * 256;
            int g = idx >> 11, r = idx & 2047, kk = r >> 6, uu = r & 63;
            const float* w = (g == 0) ? wxi : ((g == 1) ? wxf : wxc);
            ws[g][kk][uu] = w[(k0 + kk) * UU + ub + uu];
        }
        __syncthreads();
#pragma unroll
        for (int kk = 0; kk < 32; ++kk) {
            unsigned long long xb[4];
#pragma unroll
            for (int i = 0; i < 4; ++i) {
                unsigned xv = __float_as_uint(xs[b0 + i][kk]);
                asm("mov.b64 %0, {%1, %1};" : "=l"(xb[i]) : "r"(xv));
            }
#pragma unroll
            for (int g = 0; g < 3; ++g) {
                const ulonglong2 wv = *(const ulonglong2*)&ws[g][kk][ul];
#pragma unroll
                for (int i = 0; i < 4; ++i) {
                    fma2(acc[g][i][0], xb[i], wv.x);
                    fma2(acc[g][i][1], xb[i], wv.y);
                }
            }
        }
        __syncthreads();
    }

    const float* biases[3] = {bi, bf, bc};
#pragma unroll
    for (int g = 0; g < 3; ++g) {
        float2 bv0 = *(const float2*)&biases[g][ub + ul];
        float2 bv1 = *(const float2*)&biases[g][ub + ul + 2];
#pragma unroll
        for (int i = 0; i < 4; ++i) {
            float2 r0 = upk(acc[g][i][0]);
            float2 r1 = upk(acc[g][i][1]);
            r0.x += bv0.x; r0.y += bv0.y;
            r1.x += bv1.x; r1.y += bv1.y;
            float* dst = &g_xp[g][t][b0 + i][ub + ul];
            *(float2*)dst = r0;
            *(float2*)(dst + 2) = r1;
        }
    }
}

// ============================================================================
// Init: h0 -> g_hbuf[1]
// ============================================================================
__global__ void init_kernel(const float* __restrict__ h0) {
    int i = blockIdx.x * blockDim.x + threadIdx.x;
    if (i < BB * UU) g_hbuf[1][i] = h0[i];
}

// ============================================================================
// Phase 2: persistent recurrent kernel. 128 CTAs x 288 threads.
// Warps 0..7 compute; warp 8 = grid-barrier poller.
// Thread (ks=tid>>4 in 0..15, bg=(tid>>1)&7, c=tid&1):
//   8 rows bg*8..+7, 6 outputs (3 gates x cols c*2,c*2+1), 32 k = slots ks*8..+7.
//   -> per k4: 8 h-LDS.128 + 6 w-LDS.128 for 96 fma2 (1.17 B/MAC).
// Warp w self-stages h slots [w*16, w*16+16) (k in [w*64,+64)), all 64 rows.
// h smem: row r at r*2048; 16B slot s stored at s ^ ((r>>3)&7); thread's rows
//   share key bg -> per-thread-constant XOR. ks-pair rotation (+2 slots)
//   keeps w and h bank groups disjoint within a warp.
// Partials: red[o*REDO + g*16 + (ks ^ (bg*2+c))], o=row*4+col; gate thread
//   tid(<256, o=tid) reads 16 contiguous floats/gate (XOR perm absorbed by sum).
// Sync per step: one __syncthreads; gates -> membar.cta + bar.arrive(1,288);
// poller: bar.sync(1,288) -> red.add.release.gpu -> poll -> smem flag release.
// ============================================================================
__global__ void __launch_bounds__(NTH, 1) lstm_kernel(
    const float* __restrict__ whi, const float* __restrict__ whf,
    const float* __restrict__ whc, const float* __restrict__ c0,
    float* __restrict__ out) {
    extern __shared__ __align__(16) char sm[];
    float* smW = (float*)(sm + W_OFF);
    float* smR = (float*)(sm + R_OFF);

    const int tid = threadIdx.x;
    const int wid = tid >> 5, lane = tid & 31;
    const int u0 = blockIdx.x * 4;
    // compute roles (tid < 256)
    const int c  = tid & 1;
    const int bg = (tid >> 1) & 7;
    const int ks = tid >> 4;                 // 0..15 (== wid*2 + ((tid>>4)&1))
    const int rot = (ks & 1) * 2;            // slot rotation for ks pairs
    // staging roles (warp-local): lane = (lr=lane>>3 in 0..3, ls=lane&7)
    const int lr = lane >> 3, ls = lane & 7;
    // gate roles (tid < 256): output o = tid = row*4 + col
    const int b2 = tid >> 2, c2 = tid & 3;
    const int u = u0 + c2;

    {
        const float* wsrc[3] = {whi, whf, whc};
        for (int i = tid; i < 3 * 4 * UU; i += NTH) {
            int cc = i & 3, k = (i >> 2) & 511, g = i >> 11;
            smW[(g * 4 + cc) * WROW + k] = wsrc[g][k * UU + u0 + cc];
        }
    }
    float cst = (tid < 256) ? c0[b2 * UU + u] : 0.0f;

    const uint32_t smbase = (uint32_t)__cvta_generic_to_shared(sm);
    const uint32_t flagaddr = smbase + FLAG_OFF;
    if (tid == 0) *(unsigned*)(sm + FLAG_OFF) = 0u;

    const int perm = bg * 2 + c;                       // ks-XOR bijection
    float* redw = smR + (bg * 8) * 4 * REDO + (c * 2) * REDO + (ks ^ perm);
    const float* redr = smR + tid * REDO;              // o = tid, 16B-aligned

    const size_t gstride = (size_t)TT * BB * UU;
    const float* xpi = &g_xp[0][0][0][0] + 0 * gstride + (size_t)b2 * UU + u;
    const float* xpf = &g_xp[0][0][0][0] + 1 * gstride + (size_t)b2 * UU + u;
    const float* xpc = &g_xp[0][0][0][0] + 2 * gstride + (size_t)b2 * UU + u;
    float* orow = out + (size_t)b2 * TT * UU + u;

    __syncthreads();

    for (int t = 0; t < TT; ++t) {
        if (tid < 256) {
            // prefetch xp(t) before the flag wait (independent of recurrence)
            float pi = __ldcg(xpi + (size_t)t * (BB * UU));
            float pf = __ldcg(xpf + (size_t)t * (BB * UU));
            float pc = __ldcg(xpc + (size_t)t * (BB * UU));

            if (t > 0) {
                unsigned v;
                do {
                    asm volatile("ld.acquire.cta.shared.u32 %0, [%1];"
                                 : "=r"(v) : "r"(flagaddr) : "memory");
                } while (v < (unsigned)t);
            }

            // stage THIS warp's h region: all 64 rows x slots [wid*16,+16)
            const float* hsrc = &g_hbuf[(t + 1) & 1][0];
#pragma unroll
            for (int j = 0; j < 32; ++j) {
                int jr = j & 15, js = j >> 4;
                int r = jr * 4 + lr;
                int s = wid * 16 + js * 8 + ls;
                uint32_t dst = smbase + r * 2048 +
                               (uint32_t)((s ^ ((r >> 3) & 7)) << 4);
                cp16(dst, hsrc + r * 512 + s * 4);
            }
            asm volatile("cp.async.commit_group;");
            asm volatile("cp.async.wait_group 0;");
            __syncwarp();

            unsigned long long acc[8][3][2];
#pragma unroll
            for (int i = 0; i < 8; ++i)
#pragma unroll
                for (int g = 0; g < 3; ++g) {
                    acc[i][g][0] = 0ull; acc[i][g][1] = 0ull;
                }

#pragma unroll
            for (int j = 0; j < 8; ++j) {
                const int k4 = ks * 8 + ((j + rot) & 7);
                ulonglong2 wv[3][2];
#pragma unroll
                for (int g = 0; g < 3; ++g)
#pragma unroll
                    for (int q = 0; q < 2; ++q)
                        wv[g][q] = *(const ulonglong2*)(
                            smW + (g * 4 + c * 2 + q) * WROW + k4 * 4);
                const uint32_t koff = (uint32_t)((k4 ^ bg) << 4);
                const char* hb = sm + (bg * 8) * 2048 + koff;
#pragma unroll
                for (int i = 0; i < 8; ++i) {
                    const ulonglong2 hv = *(const ulonglong2*)(hb + i * 2048);
#pragma unroll
                    for (int g = 0; g < 3; ++g) {
#pragma unroll
                        for (int q = 0; q < 2; ++q) {
                            fma2(acc[i][g][q], hv.x, wv[g][q].x);
                            fma2(acc[i][g][q], hv.y, wv[g][q].y);
                        }
                    }
                }
            }

            // partial writes: red[(bg*8+i)*4*REDO + (c*2+q)*REDO + g*16 + ks^perm]
#pragma unroll
            for (int i = 0; i < 8; ++i)
#pragma unroll
                for (int g = 0; g < 3; ++g)
#pragma unroll
                    for (int q = 0; q < 2; ++q) {
                        float2 v = upk(acc[i][g][q]);
                        redw[i * 4 * REDO + q * REDO + g * 16] = v.x + v.y;
                    }
            __syncthreads();

            // reduce + gates: 16 contiguous partials per gate
            float s[3];
#pragma unroll
            for (int g = 0; g < 3; ++g) {
                const float* rb = redr + g * 16;
                float4 a = *(const float4*)(rb + 0);
                float4 b = *(const float4*)(rb + 4);
                float4 d = *(const float4*)(rb + 8);
                float4 e = *(const float4*)(rb + 12);
                s[g] = (((a.x + a.y) + (a.z + a.w)) + ((b.x + b.y) + (b.z + b.w)))
                     + (((d.x + d.y) + (d.z + d.w)) + ((e.x + e.y) + (e.z + e.w)));
            }
            float ig = fsig(pi + s[0]);
            float fg = fsig(pf + s[1]);
            float cin = ftanh(pc + s[2]);
            cst = fg * cst + ig * cin;
            float hn = ftanh(cst);
            __stcg(&g_hbuf[t & 1][b2 * UU + u], hn);
            orow[(size_t)t * UU] = hn;

            if (t < TT - 1) {
                asm volatile("membar.cta;" ::: "memory");
                asm volatile("bar.arrive 1, %0;" :: "n"(NTH) : "memory");
            }
        } else {
            __syncthreads();
            if (t < TT - 1) {
                asm volatile("bar.sync 1, %0;" :: "n"(NTH) : "memory");
                if (lane == 0) {
                    asm volatile("red.release.gpu.global.add.u32 [%0], 1;"
                                 :: "l"(&g_count) : "memory");
                    unsigned target = (unsigned)(t + 1) * NCTA;
                    unsigned v;
                    do {
                        asm volatile("ld.acquire.gpu.u32 %0, [%1];"
                                     : "=r"(v) : "l"(&g_count) : "memory");
                    } while (v < target);
                    asm volatile("st.release.cta.shared.u32 [%0], %1;"
                                 :: "r"(flagaddr), "r"((unsigned)(t + 1))
                                 : "memory");
                }
                __syncwarp();
            }
        }
    }
}

extern "C" void kernel_launch(void* const* d_in, const int* in_sizes, int n_in,
                              void* d_out, int out_size) {
    const float* x   = (const float*)d_in[0];
    const float* wxi = (const float*)d_in[1];
    const float* wxf = (const float*)d_in[2];
    const float* wxc = (const float*)d_in[3];
    const float* whi = (const float*)d_in[4];
    const float* whf = (const float*)d_in[5];
    const float* whc = (const float*)d_in[6];
    const float* bi  = (const float*)d_in[7];
    const float* bf  = (const float*)d_in[8];
    const float* bc  = (const float*)d_in[9];
    const float* h0  = (const float*)d_in[10];
    const float* c0  = (const float*)d_in[11];
    float* out = (float*)d_out;

    cudaFuncSetAttribute(lstm_kernel, cudaFuncAttributeMaxDynamicSharedMemorySize,
                         SM_TOTAL);

    proj_kernel<<<dim3(8, TT), 256>>>(x, wxi, wxf, wxc, bi, bf, bc);
    init_kernel<<<(BB * UU + 255) / 256, 256>>>(h0);
    lstm_kernel<<<NCTA, NTH, SM_TOTAL>>>(whi, whf, whc, c0, out);
}